// round 15
// baseline (speedup 1.0000x reference)
#include <cuda_runtime.h>
#include <stdint.h>

#define Bn 32
#define In 1152
#define On 10
#define Dn 16
#define Hn 10
#define Sn 922
#define NBO (Bn * On)            // 320 (b,o) tasks
#define NROWS (Bn * In * On)     // 368,640 u-rows

// ---- global scratch (device globals: allocation-free, zero at load) ----
__device__ float    g_w [NROWS];          // ||u_row||,  indexed (b*In+i)*On+o
__device__ float    g_w2[NROWS];          // ||u_row||^2
__device__ float    g_Mu[(size_t)NBO * Hn * Dn];   // [bo][h][d]
__device__ float    g_losses[(size_t)NBO * Hn];
__device__ unsigned g_tick[NBO];          // INVARIANT: zero at entry (reset each use)

__device__ __forceinline__ float fsqrt_mufu(float x) {
    return x * __frsqrt_rn(fmaxf(x, 1e-35f));
}

// ============ KA: row norms (coalesced stream over u, no transpose) ============
__global__ void __launch_bounds__(256)
kA_norms(const float* __restrict__ up)
{
    int e = blockIdx.x * 256 + threadIdx.x;          // float4 id, 1,474,560 total
    int q = e & 3;
    int t = e >> 2;                                  // row id = (b*In+i)*On+o
    float4 v = reinterpret_cast<const float4*>(up)[e];
    float s = v.x * v.x + v.y * v.y + v.z * v.z + v.w * v.w;
    s += __shfl_xor_sync(0xffffffffu, s, 1);
    s += __shfl_xor_sync(0xffffffffu, s, 2);
    if (q == 0) {
        g_w2[t] = s;
        g_w[t]  = fsqrt_mufu(s);
    }
}

// ============ KBC: per (bo,h): gather-Mu + loss + ticket argmin ============
__global__ void __launch_bounds__(128)
kBC_main(const float* __restrict__ up, const int* __restrict__ sidx32,
         float* __restrict__ out)
{
    __shared__ float snum[4][Dn];
    __shared__ float sden[4];
    __shared__ __align__(16) float sMu[Dn];
    __shared__ float smm;
    __shared__ float spart[4];
    __shared__ int s_is64, s_last, s_best;

    const int tid = threadIdx.x;
    const int bo = blockIdx.x, h = blockIdx.y;
    const int b = bo / On, o = bo % On;
    const int lane = tid & 31, wrp = tid >> 5;
    const int d = tid & 15, sp = tid >> 4;           // d-lane, s-partition (0..7)

    if (tid == 0) {
        int all0 = 1;                    // int64 -> odd words all 0 (idx < 1152)
        #pragma unroll
        for (int k = 0; k < 8; k++) all0 &= (sidx32[2 * k + 1] == 0);
        s_is64 = all0;
    }
    __syncthreads();
    const int is64 = s_is64;

    // ---- gather phase: num_d = sum_s w[i_s]*u[i_s][d], den = sum_s w[i_s] ----
    // sample_idx[b,s,o,h] element offset: ((b*Sn + s)*On + o)*Hn + h
    float num = 0.f, den = 0.f;
    {
        const size_t ibase = ((size_t)b * Sn * On + o) * Hn + h;
        #pragma unroll 4
        for (int s = sp; s < Sn; s += 8) {           // 115-116 iters (uniform per warp)
            size_t eo = ibase + (size_t)s * (On * Hn);
            int i = is64 ? sidx32[eo << 1] : sidx32[eo];
            i = min(max(i, 0), In - 1);              // never fault
            int row = (b * In + i) * On + o;
            float wv = g_w[row];
            float uv = up[row * Dn + d];
            num = fmaf(wv, uv, num);
            den += wv;
        }
    }
    // lanes d and d+16 (sp pair within warp) combine
    num += __shfl_xor_sync(0xffffffffu, num, 16);
    den += __shfl_xor_sync(0xffffffffu, den, 16);
    if (lane < Dn) {
        snum[wrp][lane] = num;
        if (lane == 0) sden[wrp] = den;
    }
    __syncthreads();
    if (tid < Dn) {
        float nt = snum[0][tid] + snum[1][tid] + snum[2][tid] + snum[3][tid];
        float dt = sden[0] + sden[1] + sden[2] + sden[3];
        float mu = nt / dt;
        sMu[tid] = mu;
        g_Mu[((size_t)bo * Hn + h) * Dn + tid] = mu;
        // mm = sum_d mu^2 across the 16 lanes
        float mm = mu * mu;
        mm += __shfl_xor_sync(0x0000ffffu, mm, 1);
        mm += __shfl_xor_sync(0x0000ffffu, mm, 2);
        mm += __shfl_xor_sync(0x0000ffffu, mm, 4);
        mm += __shfl_xor_sync(0x0000ffffu, mm, 8);
        if (tid == 0) smm = mm;
    }
    __syncthreads();

    // ---- loss phase: losses[bo][h] = sum_i sqrt(w2 - 2*dot(u_i,Mu) + mm) ----
    const float4 m0 = reinterpret_cast<const float4*>(sMu)[0];
    const float4 m1 = reinterpret_cast<const float4*>(sMu)[1];
    const float4 m2 = reinterpret_cast<const float4*>(sMu)[2];
    const float4 m3 = reinterpret_cast<const float4*>(sMu)[3];
    const float mmv = smm;

    float lloc = 0.f;
    #pragma unroll
    for (int k = 0; k < In / 128; k++) {             // 9 exact iters
        int i = tid + k * 128;
        int row = (b * In + i) * On + o;
        const float4* u4 = reinterpret_cast<const float4*>(up + (size_t)row * Dn);
        float4 a  = u4[0], b4 = u4[1], c = u4[2], d4 = u4[3];
        float ww2 = g_w2[row];
        float d0 = a.x * m0.x;
        float d1 = a.y * m0.y;
        d0 = fmaf(a.z, m0.z, d0);   d1 = fmaf(a.w, m0.w, d1);
        d0 = fmaf(b4.x, m1.x, d0);  d1 = fmaf(b4.y, m1.y, d1);
        d0 = fmaf(b4.z, m1.z, d0);  d1 = fmaf(b4.w, m1.w, d1);
        d0 = fmaf(c.x, m2.x, d0);   d1 = fmaf(c.y, m2.y, d1);
        d0 = fmaf(c.z, m2.z, d0);   d1 = fmaf(c.w, m2.w, d1);
        d0 = fmaf(d4.x, m3.x, d0);  d1 = fmaf(d4.y, m3.y, d1);
        d0 = fmaf(d4.z, m3.z, d0);  d1 = fmaf(d4.w, m3.w, d1);
        float s = fmaf(-2.0f, d0 + d1, ww2 + mmv);
        lloc += fsqrt_mufu(fmaxf(s, 0.0f));
    }
    #pragma unroll
    for (int off = 1; off <= 16; off <<= 1)
        lloc += __shfl_xor_sync(0xffffffffu, lloc, off);
    if (lane == 0) spart[wrp] = lloc;
    __syncthreads();
    if (tid == 0)
        g_losses[(size_t)bo * Hn + h] = spart[0] + spart[1] + spart[2] + spart[3];

    // ---- ticket: last h-CTA of this bo does argmin + gather output ----
    __threadfence();
    __syncthreads();
    if (tid == 0) {
        unsigned old = atomicAdd(&g_tick[bo], 1u);
        s_last = (old == Hn - 1);
    }
    __syncthreads();
    if (!s_last) return;
    if (tid == 0) {
        g_tick[bo] = 0u;                             // reset for next graph replay
        int best = 0; float bv = g_losses[(size_t)bo * Hn];
        #pragma unroll
        for (int hh = 1; hh < Hn; hh++) {            // fixed order -> deterministic
            float v = g_losses[(size_t)bo * Hn + hh];
            if (v < bv) { bv = v; best = hh; }
        }
        s_best = best;
    }
    __syncthreads();
    if (tid < Dn)
        out[(size_t)bo * Dn + tid] = g_Mu[((size_t)bo * Hn + s_best) * Dn + tid];
}

extern "C" void kernel_launch(void* const* d_in, const int* in_sizes, int n_in,
                              void* d_out, int out_size)
{
    const float* up;
    const int* si;
    if (in_sizes[0] == Bn * In * On * Dn) {
        up = (const float*)d_in[0];
        si = (const int*)d_in[1];
    } else {
        up = (const float*)d_in[1];
        si = (const int*)d_in[0];
    }
    float* out = (float*)d_out;

    kA_norms<<<(NROWS * 4) / 256, 256>>>(up);        // 5760 CTAs, streaming
    kBC_main<<<dim3(NBO, Hn), 128>>>(up, si, out);   // 3200 CTAs
}